// round 11
// baseline (speedup 1.0000x reference)
#include <cuda_runtime.h>
#include <cuda_fp16.h>

typedef unsigned long long ull;

#define DQ    512
#define H1Q   16
#define CQ    40
#define N_MAX 100000
#define NNZ_MAX 3200000
#define SCAN_B 1024
#define NBLK_SCAN ((N_MAX + SCAN_B - 1) / SCAN_B)   // 98

#define TK     8                  // k-cols per tile
#define NT     (DQ / TK)          // 64 tiles
#define PADW   12                 // floats per staged row (8 + 4 pad)

// ------------------------------ scratch -------------------------------------
__device__ uint2 g_X1h[N_MAX * 4];           // H @ W1, fp16
__device__ uint2 g_Zh [N_MAX * 4];           // relu(A @ X1 + b1), fp16
__device__ int   g_cnt[N_MAX];
__device__ int   g_ptr[N_MAX];
__device__ int   g_cur[N_MAX];
__device__ int   g_part[NBLK_SCAN];
__device__ int2  g_edges[NNZ_MAX];           // {col, val_bits} CSR-ordered

// ------------------------------ helpers -------------------------------------
__device__ __forceinline__ ull fma2(ull a, ull b, ull c) {
    ull d;
    asm("fma.rn.f32x2 %0, %1, %2, %3;" : "=l"(d) : "l"(a), "l"(b), "l"(c));
    return d;
}
__device__ __forceinline__ ull pack2(float x) {
    ull d;
    asm("mov.b64 %0, {%1, %1};" : "=l"(d) : "f"(x));
    return d;
}
__device__ __forceinline__ float2 unpack2(ull v) {
    float a, b;
    asm("mov.b64 {%0, %1}, %2;" : "=f"(a), "=f"(b) : "l"(v));
    return make_float2(a, b);
}
__device__ __forceinline__ unsigned h2pack(ull v) {
    float2 f = unpack2(v);
    __half2 h = __float22half2_rn(f);
    return *reinterpret_cast<unsigned*>(&h);
}
__device__ __forceinline__ float2 h2unpack(unsigned u) {
    __half2 h = *reinterpret_cast<__half2*>(&u);
    return __half22float2(h);
}
__device__ __forceinline__ unsigned smem_u32(const void* p) {
    return (unsigned)__cvta_generic_to_shared(p);
}
__device__ __forceinline__ void cp_async16(unsigned s, const void* g) {
    asm volatile("cp.async.cg.shared.global [%0], [%1], 16;" :: "r"(s), "l"(g));
}
__device__ __forceinline__ void cp_commit() {
    asm volatile("cp.async.commit_group;");
}
template <int N>
__device__ __forceinline__ void cp_wait() {
    asm volatile("cp.async.wait_group %0;" :: "n"(N));
}

// ------------------------------ hist ----------------------------------------
__global__ void hist_kernel(const int* __restrict__ rows, int nnz) {
    int idx = blockIdx.x * blockDim.x + threadIdx.x;
    int nv = nnz >> 2;
    if (idx < nv) {
        int4 r4 = reinterpret_cast<const int4*>(rows)[idx];
        atomicAdd(&g_cnt[r4.x], 1);
        atomicAdd(&g_cnt[r4.y], 1);
        atomicAdd(&g_cnt[r4.z], 1);
        atomicAdd(&g_cnt[r4.w], 1);
    } else if (idx == nv) {
        for (int e = nv * 4; e < nnz; e++) atomicAdd(&g_cnt[rows[e]], 1);
    }
}

// ------------------------------ scans ---------------------------------------
__global__ void scan1_kernel(int n) {
    __shared__ int s[SCAN_B];
    int tid = threadIdx.x;
    int i = blockIdx.x * SCAN_B + tid;
    int v = (i < n) ? g_cnt[i] : 0;
    s[tid] = v;
    __syncthreads();
#pragma unroll
    for (int off = 1; off < SCAN_B; off <<= 1) {
        int t = 0;
        if (tid >= off) t = s[tid - off];
        __syncthreads();
        if (tid >= off) s[tid] += t;
        __syncthreads();
    }
    if (i < n) g_ptr[i] = s[tid] - v;
    if (tid == SCAN_B - 1) g_part[blockIdx.x] = s[SCAN_B - 1];
}

__global__ void scan23_kernel(int n, int nb) {
    __shared__ int s[128];
    int tid = threadIdx.x;
    if (tid < 128) s[tid] = (tid < nb) ? g_part[tid] : 0;
    __syncthreads();
#pragma unroll
    for (int off = 1; off < 128; off <<= 1) {
        int u = 0;
        if (tid < 128 && tid >= off) u = s[tid - off];
        __syncthreads();
        if (tid < 128 && tid >= off) s[tid] += u;
        __syncthreads();
    }
    int i = blockIdx.x * blockDim.x + tid;
    if (i < n) {
        int blk = i >> 10;
        int base = (blk == 0) ? 0 : s[blk - 1];
        int p = g_ptr[i] + base;
        g_ptr[i] = p;
        g_cur[i] = p;
    }
}

// ------------------------------ fused GEMM + scatter -------------------------
// gemm: 8 per-warp pipelines; warp owns 64 rows (2 rows/thread), TK=8,
// double-buffered cp.async. W1 read via uniform __ldg (L1-resident broadcast)
// -> no W smem, no block barrier, 48KB smem total. scatter: 4 edges/thread.
__global__ void __launch_bounds__(256, 3) gemm_scatter_kernel(
        const float* __restrict__ Hm, const float* __restrict__ W1,
        const int* __restrict__ rows, const int* __restrict__ cols,
        const float* __restrict__ vals, int n, int nnz, int gemm_blocks) {
    __shared__ float sH[8][2][64 * PADW];       // 8 x 6KB = 48KB

    if ((int)blockIdx.x < gemm_blocks) {
        int tid  = threadIdx.x;
        int warp = tid >> 5;
        int lane = tid & 31;
        int rbase = (blockIdx.x * 8 + warp) * 64;
        int ra = rbase + lane;
        int rb = ra + 32;

        // stage tile 0
#pragma unroll
        for (int j = 0; j < 4; j++) {
            int i = lane + 32 * j;
            int r = i >> 1, q = i & 1;
            int grow = rbase + r;
            if (grow < n)
                cp_async16(smem_u32(&sH[warp][0][r * PADW + q * 4]),
                           Hm + (size_t)grow * DQ + q * 4);
        }
        cp_commit();

        ull accA[8], accB[8];
        ull z = pack2(0.f);
#pragma unroll
        for (int p = 0; p < 8; p++) { accA[p] = z; accB[p] = z; }

        const ulonglong2* __restrict__ wv =
            reinterpret_cast<const ulonglong2*>(W1);

        for (int t = 0; t < NT; t++) {
            int buf = t & 1;
            if (t + 1 < NT) {
#pragma unroll
                for (int j = 0; j < 4; j++) {
                    int i = lane + 32 * j;
                    int r = i >> 1, q = i & 1;
                    int grow = rbase + r;
                    if (grow < n)
                        cp_async16(smem_u32(&sH[warp][buf ^ 1][r * PADW + q * 4]),
                                   Hm + (size_t)grow * DQ + (t + 1) * TK + q * 4);
                }
                cp_commit();
                cp_wait<1>();
            } else {
                cp_wait<0>();
            }
            __syncwarp();

            const float* hrA = &sH[warp][buf][lane * PADW];
            const float* hrB = &sH[warp][buf][(lane + 32) * PADW];
#pragma unroll
            for (int q = 0; q < 2; q++) {
                float4 hA = *reinterpret_cast<const float4*>(hrA + q * 4);
                float4 hB = *reinterpret_cast<const float4*>(hrB + q * 4);
                float a4[4] = {hA.x, hA.y, hA.z, hA.w};
                float b4[4] = {hB.x, hB.y, hB.z, hB.w};
#pragma unroll
                for (int j = 0; j < 4; j++) {
                    int k = t * TK + q * 4 + j;
                    ull pa = pack2(a4[j]);
                    ull pb = pack2(b4[j]);
#pragma unroll
                    for (int p = 0; p < 4; p++) {
                        ulonglong2 w = __ldg(&wv[k * 4 + p]);
                        accA[2 * p + 0] = fma2(pa, w.x, accA[2 * p + 0]);
                        accA[2 * p + 1] = fma2(pa, w.y, accA[2 * p + 1]);
                        accB[2 * p + 0] = fma2(pb, w.x, accB[2 * p + 0]);
                        accB[2 * p + 1] = fma2(pb, w.y, accB[2 * p + 1]);
                    }
                }
            }
            __syncwarp();
        }

        if (ra < n) {
            uint2* o = &g_X1h[(size_t)ra * 4];
#pragma unroll
            for (int q = 0; q < 4; q++)
                o[q] = make_uint2(h2pack(accA[2 * q]), h2pack(accA[2 * q + 1]));
        }
        if (rb < n) {
            uint2* o = &g_X1h[(size_t)rb * 4];
#pragma unroll
            for (int q = 0; q < 4; q++)
                o[q] = make_uint2(h2pack(accB[2 * q]), h2pack(accB[2 * q + 1]));
        }
    } else {
        int idx = (blockIdx.x - gemm_blocks) * 256 + threadIdx.x;
        int nv = nnz >> 2;
        if (idx < nv) {
            int4   r4 = reinterpret_cast<const int4*>(rows)[idx];
            int4   c4 = reinterpret_cast<const int4*>(cols)[idx];
            float4 v4 = reinterpret_cast<const float4*>(vals)[idx];
            int p0 = atomicAdd(&g_cur[r4.x], 1);
            int p1 = atomicAdd(&g_cur[r4.y], 1);
            int p2 = atomicAdd(&g_cur[r4.z], 1);
            int p3 = atomicAdd(&g_cur[r4.w], 1);
            g_edges[p0] = make_int2(c4.x, __float_as_int(v4.x));
            g_edges[p1] = make_int2(c4.y, __float_as_int(v4.y));
            g_edges[p2] = make_int2(c4.z, __float_as_int(v4.z));
            g_edges[p3] = make_int2(c4.w, __float_as_int(v4.w));
        } else if (idx == nv) {
            for (int e = nv * 4; e < nnz; e++) {
                int p = atomicAdd(&g_cur[rows[e]], 1);
                g_edges[p] = make_int2(cols[e], __float_as_int(vals[e]));
            }
        }
    }
}

// ------------------------------ SpMM gather core (MLP=8) ---------------------
__device__ __forceinline__ float4 gather_row(const uint2* __restrict__ X,
                                             const int2* __restrict__ ed,
                                             int deg, int sub) {
    float4 acc = make_float4(0, 0, 0, 0);
    int i = 0;
    for (; i + 8 <= deg; i += 8) {
        int2  e[8];
        uint2 x[8];
#pragma unroll
        for (int j = 0; j < 8; j++) e[j] = ed[i + j];
#pragma unroll
        for (int j = 0; j < 8; j++) x[j] = X[(size_t)e[j].x * 4 + sub];
#pragma unroll
        for (int j = 0; j < 8; j++) {
            float v = __int_as_float(e[j].y);
            float2 lo = h2unpack(x[j].x), hi = h2unpack(x[j].y);
            acc.x = fmaf(v, lo.x, acc.x); acc.y = fmaf(v, lo.y, acc.y);
            acc.z = fmaf(v, hi.x, acc.z); acc.w = fmaf(v, hi.y, acc.w);
        }
    }
    for (; i < deg; i++) {
        int2 e = ed[i];
        float v = __int_as_float(e.y);
        uint2 xh = X[(size_t)e.x * 4 + sub];
        float2 lo = h2unpack(xh.x), hi = h2unpack(xh.y);
        acc.x = fmaf(v, lo.x, acc.x); acc.y = fmaf(v, lo.y, acc.y);
        acc.z = fmaf(v, hi.x, acc.z); acc.w = fmaf(v, hi.y, acc.w);
    }
    return acc;
}

// ------------------------------ SpMM 1 ---------------------------------------
__global__ void spmm1_kernel(const float* __restrict__ b1, int n) {
    int wg   = (blockIdx.x * blockDim.x + threadIdx.x) >> 5;
    int lane = threadIdx.x & 31;
    int rloc = lane >> 2, sub = lane & 3;
    int row  = wg * 8 + rloc;
    if (row >= n) return;

    int start = g_ptr[row];
    int deg   = g_cnt[row];
    const float4 b = reinterpret_cast<const float4*>(b1)[sub];

    float4 acc = gather_row(g_X1h, g_edges + start, deg, sub);

    float2 z0 = make_float2(fmaxf(acc.x + b.x, 0.f), fmaxf(acc.y + b.y, 0.f));
    float2 z1 = make_float2(fmaxf(acc.z + b.z, 0.f), fmaxf(acc.w + b.w, 0.f));
    __half2 h0 = __float22half2_rn(z0);
    __half2 h1 = __float22half2_rn(z1);
    g_Zh[(size_t)row * 4 + sub] =
        make_uint2(*reinterpret_cast<unsigned*>(&h0), *reinterpret_cast<unsigned*>(&h1));
}

// ------------------------------ SpMM 2 + epilogue ----------------------------
__global__ void __launch_bounds__(256) spmm2_epi_kernel(
        const float* __restrict__ W2, const float* __restrict__ b2,
        float* __restrict__ out, int n) {
    __shared__ float sY[64 * 17];
    __shared__ float sW[H1Q * CQ];
    __shared__ float sB[CQ];

    for (int i = threadIdx.x; i < H1Q * CQ; i += blockDim.x) sW[i] = W2[i];
    if (threadIdx.x < CQ) sB[threadIdx.x] = b2[threadIdx.x];

    int warp  = threadIdx.x >> 5;
    int lane  = threadIdx.x & 31;
    int rloc  = warp * 8 + (lane >> 2);
    int sub   = lane & 3;
    int rbase = blockIdx.x * 64;
    int row   = rbase + rloc;

    float4 acc = make_float4(0, 0, 0, 0);
    if (row < n) {
        acc = gather_row(g_Zh, g_edges + g_ptr[row], g_cnt[row], sub);
    }
    float* sy = &sY[rloc * 17 + sub * 4];
    sy[0] = acc.x; sy[1] = acc.y; sy[2] = acc.z; sy[3] = acc.w;
    __syncthreads();

    // epilogue: thread t -> row t>>2, columns [10*(t&3), 10*(t&3)+10)
    int t    = threadIdx.x;
    int erow = t >> 2;
    int part = t & 3;
    if (rbase + erow < n) {
        float y[16];
#pragma unroll
        for (int k = 0; k < 16; k++) y[k] = sY[erow * 17 + k];

        float o[10];
#pragma unroll
        for (int c = 0; c < 10; c++) o[c] = sB[part * 10 + c];
#pragma unroll
        for (int k = 0; k < H1Q; k++) {
            float h = y[k];
#pragma unroll
            for (int c = 0; c < 10; c++)
                o[c] = fmaf(h, sW[k * CQ + part * 10 + c], o[c]);
        }
        float m = 0.f;                      // relu floor
#pragma unroll
        for (int c = 0; c < 10; c++) {
            o[c] = fmaxf(o[c], 0.f);
            m = fmaxf(m, o[c]);
        }
        m = fmaxf(m, __shfl_xor_sync(0xffffffffu, m, 1));
        m = fmaxf(m, __shfl_xor_sync(0xffffffffu, m, 2));
        float s = 0.f;
#pragma unroll
        for (int c = 0; c < 10; c++) s += __expf(o[c] - m);
        s += __shfl_xor_sync(0xffffffffu, s, 1);
        s += __shfl_xor_sync(0xffffffffu, s, 2);
        float l = __logf(s) + m;

        float2* op = reinterpret_cast<float2*>(
            out + (size_t)(rbase + erow) * CQ + part * 10);
#pragma unroll
        for (int q = 0; q < 5; q++)
            op[q] = make_float2(o[2 * q] - l, o[2 * q + 1] - l);
    }
}

// ---------------------------------------------------------------------------
// Inputs (metadata order): H, A_vals, W1, b1, W2, b2, A_rows, A_cols
// ---------------------------------------------------------------------------
extern "C" void kernel_launch(void* const* d_in, const int* in_sizes, int n_in,
                              void* d_out, int out_size) {
    const float* Hm     = (const float*)d_in[0];
    const float* A_vals = (const float*)d_in[1];
    const float* W1     = (const float*)d_in[2];
    const float* b1     = (const float*)d_in[3];
    const float* W2     = (const float*)d_in[4];
    const float* b2     = (const float*)d_in[5];
    const int*   A_rows = (const int*)d_in[6];
    const int*   A_cols = (const int*)d_in[7];

    int n   = in_sizes[0] / DQ;
    int nnz = in_sizes[1];
    float* out = (float*)d_out;

    int nb_scan = (n + SCAN_B - 1) / SCAN_B;

    void* cnt_ptr = nullptr;
    cudaGetSymbolAddress(&cnt_ptr, g_cnt);
    cudaMemsetAsync(cnt_ptr, 0, (size_t)n * sizeof(int), 0);

    hist_kernel<<<(nnz / 4 + 256) / 256, 256>>>(A_rows, nnz);
    scan1_kernel<<<nb_scan, SCAN_B>>>(n);
    scan23_kernel<<<(n + 255) / 256, 256>>>(n, nb_scan);

    int gemm_blocks    = (n + 511) / 512;
    int scatter_blocks = (nnz / 4 + 256) / 256;
    gemm_scatter_kernel<<<gemm_blocks + scatter_blocks, 256>>>(
        Hm, W1, A_rows, A_cols, A_vals, n, nnz, gemm_blocks);

    spmm1_kernel<<<(n + 63) / 64, 256>>>(b1, n);
    spmm2_epi_kernel<<<(n + 63) / 64, 256>>>(W2, b2, out, n);
}

// round 12
// speedup vs baseline: 1.4436x; 1.4436x over previous
#include <cuda_runtime.h>
#include <cuda_fp16.h>

typedef unsigned long long ull;

#define DQ    512
#define H1Q   16
#define CQ    40
#define N_MAX 100000
#define NNZ_MAX 3200000
#define SCAN_B 1024
#define NBLK_SCAN ((N_MAX + SCAN_B - 1) / SCAN_B)   // 98

#define TK     8                  // k-cols per tile
#define NT     (DQ / TK)          // 64 tiles
#define PADW   12                 // floats per staged row (8 + 4 pad)

// ------------------------------ scratch -------------------------------------
__device__ uint2 g_X1h[N_MAX * 4];           // H @ W1, fp16
__device__ uint2 g_Zh [N_MAX * 4];           // relu(A @ X1 + b1), fp16
__device__ int   g_cnt[N_MAX];
__device__ int   g_ptr[N_MAX];
__device__ int   g_cur[N_MAX];
__device__ int   g_part[NBLK_SCAN];
__device__ int2  g_edges[NNZ_MAX];           // {col, val_bits} CSR-ordered

// ------------------------------ helpers -------------------------------------
__device__ __forceinline__ ull fma2(ull a, ull b, ull c) {
    ull d;
    asm("fma.rn.f32x2 %0, %1, %2, %3;" : "=l"(d) : "l"(a), "l"(b), "l"(c));
    return d;
}
__device__ __forceinline__ ull pack2(float x) {
    ull d;
    asm("mov.b64 %0, {%1, %1};" : "=l"(d) : "f"(x));
    return d;
}
__device__ __forceinline__ float2 unpack2(ull v) {
    float a, b;
    asm("mov.b64 {%0, %1}, %2;" : "=f"(a), "=f"(b) : "l"(v));
    return make_float2(a, b);
}
__device__ __forceinline__ unsigned h2pack(ull v) {
    float2 f = unpack2(v);
    __half2 h = __float22half2_rn(f);
    return *reinterpret_cast<unsigned*>(&h);
}
__device__ __forceinline__ float2 h2unpack(unsigned u) {
    __half2 h = *reinterpret_cast<__half2*>(&u);
    return __half22float2(h);
}
__device__ __forceinline__ unsigned smem_u32(const void* p) {
    return (unsigned)__cvta_generic_to_shared(p);
}
__device__ __forceinline__ void cp_async16(unsigned s, const void* g) {
    asm volatile("cp.async.cg.shared.global [%0], [%1], 16;" :: "r"(s), "l"(g));
}
__device__ __forceinline__ void cp_commit() {
    asm volatile("cp.async.commit_group;");
}
template <int N>
__device__ __forceinline__ void cp_wait() {
    asm volatile("cp.async.wait_group %0;" :: "n"(N));
}

// ------------------------------ hist ----------------------------------------
__global__ void hist_kernel(const int* __restrict__ rows, int nnz) {
    int idx = blockIdx.x * blockDim.x + threadIdx.x;
    int nv = nnz >> 2;
    if (idx < nv) {
        int4 r4 = reinterpret_cast<const int4*>(rows)[idx];
        atomicAdd(&g_cnt[r4.x], 1);
        atomicAdd(&g_cnt[r4.y], 1);
        atomicAdd(&g_cnt[r4.z], 1);
        atomicAdd(&g_cnt[r4.w], 1);
    } else if (idx == nv) {
        for (int e = nv * 4; e < nnz; e++) atomicAdd(&g_cnt[rows[e]], 1);
    }
}

// ------------------------------ scans ---------------------------------------
__global__ void scan1_kernel(int n) {
    __shared__ int s[SCAN_B];
    int tid = threadIdx.x;
    int i = blockIdx.x * SCAN_B + tid;
    int v = (i < n) ? g_cnt[i] : 0;
    s[tid] = v;
    __syncthreads();
#pragma unroll
    for (int off = 1; off < SCAN_B; off <<= 1) {
        int t = 0;
        if (tid >= off) t = s[tid - off];
        __syncthreads();
        if (tid >= off) s[tid] += t;
        __syncthreads();
    }
    if (i < n) g_ptr[i] = s[tid] - v;
    if (tid == SCAN_B - 1) g_part[blockIdx.x] = s[SCAN_B - 1];
}

__global__ void scan23_kernel(int n, int nb) {
    __shared__ int s[128];
    int tid = threadIdx.x;
    if (tid < 128) s[tid] = (tid < nb) ? g_part[tid] : 0;
    __syncthreads();
#pragma unroll
    for (int off = 1; off < 128; off <<= 1) {
        int u = 0;
        if (tid < 128 && tid >= off) u = s[tid - off];
        __syncthreads();
        if (tid < 128 && tid >= off) s[tid] += u;
        __syncthreads();
    }
    int i = blockIdx.x * blockDim.x + tid;
    if (i < n) {
        int blk = i >> 10;
        int base = (blk == 0) ? 0 : s[blk - 1];
        int p = g_ptr[i] + base;
        g_ptr[i] = p;
        g_cur[i] = p;
    }
}

// ------------------------------ fused GEMM + scatter -------------------------
// gemm blocks (R9 config): 8 per-warp pipelines; warp owns 64 rows (2 rows/
// thread), TK=8, double-buffered cp.async, W1 broadcast from smem.
// scatter blocks: 8 edges/thread (MLP=8).
__global__ void __launch_bounds__(256) gemm_scatter_kernel(
        const float* __restrict__ Hm, const float* __restrict__ W1,
        const int* __restrict__ rows, const int* __restrict__ cols,
        const float* __restrict__ vals, int n, int nnz, int gemm_blocks) {
    __shared__ ull   sW2[DQ * 8];               // 32KB  [k][pair0..7]
    __shared__ float sH[8][2][64 * PADW];       // 8 x 6KB

    if ((int)blockIdx.x < gemm_blocks) {
        int tid  = threadIdx.x;
        int warp = tid >> 5;
        int lane = tid & 31;
        int rbase = (blockIdx.x * 8 + warp) * 64;
        int ra = rbase + lane;
        int rb = ra + 32;

        // W via cp.async (group 0)
#pragma unroll
        for (int j = 0; j < 8; j++) {
            int i = tid + 256 * j;
            cp_async16(smem_u32(reinterpret_cast<float4*>(sW2) + i),
                       reinterpret_cast<const float4*>(W1) + i);
        }
        // stage tile 0 (group 0)
#pragma unroll
        for (int j = 0; j < 4; j++) {
            int i = lane + 32 * j;
            int r = i >> 1, q = i & 1;
            int grow = rbase + r;
            if (grow < n)
                cp_async16(smem_u32(&sH[warp][0][r * PADW + q * 4]),
                           Hm + (size_t)grow * DQ + q * 4);
        }
        cp_commit();

        ull accA[8], accB[8];
        ull z = pack2(0.f);
#pragma unroll
        for (int p = 0; p < 8; p++) { accA[p] = z; accB[p] = z; }

        const ulonglong2* wv = reinterpret_cast<const ulonglong2*>(sW2);

        for (int t = 0; t < NT; t++) {
            int buf = t & 1;
            if (t + 1 < NT) {
#pragma unroll
                for (int j = 0; j < 4; j++) {
                    int i = lane + 32 * j;
                    int r = i >> 1, q = i & 1;
                    int grow = rbase + r;
                    if (grow < n)
                        cp_async16(smem_u32(&sH[warp][buf ^ 1][r * PADW + q * 4]),
                                   Hm + (size_t)grow * DQ + (t + 1) * TK + q * 4);
                }
                cp_commit();
                cp_wait<1>();
            } else {
                cp_wait<0>();
            }
            __syncwarp();
            if (t == 0) __syncthreads();         // W visible to all warps

            const float* hrA = &sH[warp][buf][lane * PADW];
            const float* hrB = &sH[warp][buf][(lane + 32) * PADW];
#pragma unroll
            for (int q = 0; q < 2; q++) {
                float4 hA = *reinterpret_cast<const float4*>(hrA + q * 4);
                float4 hB = *reinterpret_cast<const float4*>(hrB + q * 4);
                float a4[4] = {hA.x, hA.y, hA.z, hA.w};
                float b4[4] = {hB.x, hB.y, hB.z, hB.w};
#pragma unroll
                for (int j = 0; j < 4; j++) {
                    int k = t * TK + q * 4 + j;
                    ull pa = pack2(a4[j]);
                    ull pb = pack2(b4[j]);
#pragma unroll
                    for (int p = 0; p < 4; p++) {
                        ulonglong2 w = wv[k * 4 + p];
                        accA[2 * p + 0] = fma2(pa, w.x, accA[2 * p + 0]);
                        accA[2 * p + 1] = fma2(pa, w.y, accA[2 * p + 1]);
                        accB[2 * p + 0] = fma2(pb, w.x, accB[2 * p + 0]);
                        accB[2 * p + 1] = fma2(pb, w.y, accB[2 * p + 1]);
                    }
                }
            }
            __syncwarp();
        }

        if (ra < n) {
            uint2* o = &g_X1h[(size_t)ra * 4];
#pragma unroll
            for (int q = 0; q < 4; q++)
                o[q] = make_uint2(h2pack(accA[2 * q]), h2pack(accA[2 * q + 1]));
        }
        if (rb < n) {
            uint2* o = &g_X1h[(size_t)rb * 4];
#pragma unroll
            for (int q = 0; q < 4; q++)
                o[q] = make_uint2(h2pack(accB[2 * q]), h2pack(accB[2 * q + 1]));
        }
    } else {
        int idx = (blockIdx.x - gemm_blocks) * 256 + threadIdx.x;
        int nv = nnz >> 3;                       // 8 edges per thread
        if (idx < nv) {
            const int4* r4p = reinterpret_cast<const int4*>(rows);
            const int4* c4p = reinterpret_cast<const int4*>(cols);
            const float4* v4p = reinterpret_cast<const float4*>(vals);
            int4   r0 = r4p[2 * idx],     r1 = r4p[2 * idx + 1];
            int4   c0 = c4p[2 * idx],     c1 = c4p[2 * idx + 1];
            float4 v0 = v4p[2 * idx],     v1 = v4p[2 * idx + 1];
            int p0 = atomicAdd(&g_cur[r0.x], 1);
            int p1 = atomicAdd(&g_cur[r0.y], 1);
            int p2 = atomicAdd(&g_cur[r0.z], 1);
            int p3 = atomicAdd(&g_cur[r0.w], 1);
            int p4 = atomicAdd(&g_cur[r1.x], 1);
            int p5 = atomicAdd(&g_cur[r1.y], 1);
            int p6 = atomicAdd(&g_cur[r1.z], 1);
            int p7 = atomicAdd(&g_cur[r1.w], 1);
            g_edges[p0] = make_int2(c0.x, __float_as_int(v0.x));
            g_edges[p1] = make_int2(c0.y, __float_as_int(v0.y));
            g_edges[p2] = make_int2(c0.z, __float_as_int(v0.z));
            g_edges[p3] = make_int2(c0.w, __float_as_int(v0.w));
            g_edges[p4] = make_int2(c1.x, __float_as_int(v1.x));
            g_edges[p5] = make_int2(c1.y, __float_as_int(v1.y));
            g_edges[p6] = make_int2(c1.z, __float_as_int(v1.z));
            g_edges[p7] = make_int2(c1.w, __float_as_int(v1.w));
        } else if (idx == nv) {
            for (int e = nv * 8; e < nnz; e++) {
                int p = atomicAdd(&g_cur[rows[e]], 1);
                g_edges[p] = make_int2(cols[e], __float_as_int(vals[e]));
            }
        }
    }
}

// ------------------------------ SpMM gather core (MLP=8) ---------------------
__device__ __forceinline__ float4 gather_row(const uint2* __restrict__ X,
                                             const int2* __restrict__ ed,
                                             int deg, int sub) {
    float4 acc = make_float4(0, 0, 0, 0);
    int i = 0;
    for (; i + 8 <= deg; i += 8) {
        int2  e[8];
        uint2 x[8];
#pragma unroll
        for (int j = 0; j < 8; j++) e[j] = ed[i + j];
#pragma unroll
        for (int j = 0; j < 8; j++) x[j] = X[(size_t)e[j].x * 4 + sub];
#pragma unroll
        for (int j = 0; j < 8; j++) {
            float v = __int_as_float(e[j].y);
            float2 lo = h2unpack(x[j].x), hi = h2unpack(x[j].y);
            acc.x = fmaf(v, lo.x, acc.x); acc.y = fmaf(v, lo.y, acc.y);
            acc.z = fmaf(v, hi.x, acc.z); acc.w = fmaf(v, hi.y, acc.w);
        }
    }
    for (; i < deg; i++) {
        int2 e = ed[i];
        float v = __int_as_float(e.y);
        uint2 xh = X[(size_t)e.x * 4 + sub];
        float2 lo = h2unpack(xh.x), hi = h2unpack(xh.y);
        acc.x = fmaf(v, lo.x, acc.x); acc.y = fmaf(v, lo.y, acc.y);
        acc.z = fmaf(v, hi.x, acc.z); acc.w = fmaf(v, hi.y, acc.w);
    }
    return acc;
}

// ------------------------------ SpMM 1 ---------------------------------------
__global__ void spmm1_kernel(const float* __restrict__ b1, int n) {
    int wg   = (blockIdx.x * blockDim.x + threadIdx.x) >> 5;
    int lane = threadIdx.x & 31;
    int rloc = lane >> 2, sub = lane & 3;
    int row  = wg * 8 + rloc;
    if (row >= n) return;

    int start = g_ptr[row];
    int deg   = g_cnt[row];
    const float4 b = reinterpret_cast<const float4*>(b1)[sub];

    float4 acc = gather_row(g_X1h, g_edges + start, deg, sub);

    float2 z0 = make_float2(fmaxf(acc.x + b.x, 0.f), fmaxf(acc.y + b.y, 0.f));
    float2 z1 = make_float2(fmaxf(acc.z + b.z, 0.f), fmaxf(acc.w + b.w, 0.f));
    __half2 h0 = __float22half2_rn(z0);
    __half2 h1 = __float22half2_rn(z1);
    g_Zh[(size_t)row * 4 + sub] =
        make_uint2(*reinterpret_cast<unsigned*>(&h0), *reinterpret_cast<unsigned*>(&h1));
}

// ------------------------------ SpMM 2 + epilogue ----------------------------
__global__ void __launch_bounds__(256) spmm2_epi_kernel(
        const float* __restrict__ W2, const float* __restrict__ b2,
        float* __restrict__ out, int n) {
    __shared__ float sY[64 * 17];
    __shared__ float sW[H1Q * CQ];
    __shared__ float sB[CQ];

    for (int i = threadIdx.x; i < H1Q * CQ; i += blockDim.x) sW[i] = W2[i];
    if (threadIdx.x < CQ) sB[threadIdx.x] = b2[threadIdx.x];

    int warp  = threadIdx.x >> 5;
    int lane  = threadIdx.x & 31;
    int rloc  = warp * 8 + (lane >> 2);
    int sub   = lane & 3;
    int rbase = blockIdx.x * 64;
    int row   = rbase + rloc;

    float4 acc = make_float4(0, 0, 0, 0);
    if (row < n) {
        acc = gather_row(g_Zh, g_edges + g_ptr[row], g_cnt[row], sub);
    }
    float* sy = &sY[rloc * 17 + sub * 4];
    sy[0] = acc.x; sy[1] = acc.y; sy[2] = acc.z; sy[3] = acc.w;
    __syncthreads();

    // epilogue: thread t -> row t>>2, columns [10*(t&3), 10*(t&3)+10)
    int t    = threadIdx.x;
    int erow = t >> 2;
    int part = t & 3;
    if (rbase + erow < n) {
        float y[16];
#pragma unroll
        for (int k = 0; k < 16; k++) y[k] = sY[erow * 17 + k];

        float o[10];
#pragma unroll
        for (int c = 0; c < 10; c++) o[c] = sB[part * 10 + c];
#pragma unroll
        for (int k = 0; k < H1Q; k++) {
            float h = y[k];
#pragma unroll
            for (int c = 0; c < 10; c++)
                o[c] = fmaf(h, sW[k * CQ + part * 10 + c], o[c]);
        }
        float m = 0.f;                      // relu floor
#pragma unroll
        for (int c = 0; c < 10; c++) {
            o[c] = fmaxf(o[c], 0.f);
            m = fmaxf(m, o[c]);
        }
        m = fmaxf(m, __shfl_xor_sync(0xffffffffu, m, 1));
        m = fmaxf(m, __shfl_xor_sync(0xffffffffu, m, 2));
        float s = 0.f;
#pragma unroll
        for (int c = 0; c < 10; c++) s += __expf(o[c] - m);
        s += __shfl_xor_sync(0xffffffffu, s, 1);
        s += __shfl_xor_sync(0xffffffffu, s, 2);
        float l = __logf(s) + m;

        float2* op = reinterpret_cast<float2*>(
            out + (size_t)(rbase + erow) * CQ + part * 10);
#pragma unroll
        for (int q = 0; q < 5; q++)
            op[q] = make_float2(o[2 * q] - l, o[2 * q + 1] - l);
    }
}

// ---------------------------------------------------------------------------
// Inputs (metadata order): H, A_vals, W1, b1, W2, b2, A_rows, A_cols
// ---------------------------------------------------------------------------
extern "C" void kernel_launch(void* const* d_in, const int* in_sizes, int n_in,
                              void* d_out, int out_size) {
    const float* Hm     = (const float*)d_in[0];
    const float* A_vals = (const float*)d_in[1];
    const float* W1     = (const float*)d_in[2];
    const float* b1     = (const float*)d_in[3];
    const float* W2     = (const float*)d_in[4];
    const float* b2     = (const float*)d_in[5];
    const int*   A_rows = (const int*)d_in[6];
    const int*   A_cols = (const int*)d_in[7];

    int n   = in_sizes[0] / DQ;
    int nnz = in_sizes[1];
    float* out = (float*)d_out;

    int nb_scan = (n + SCAN_B - 1) / SCAN_B;

    void* cnt_ptr = nullptr;
    cudaGetSymbolAddress(&cnt_ptr, g_cnt);
    cudaMemsetAsync(cnt_ptr, 0, (size_t)n * sizeof(int), 0);

    hist_kernel<<<(nnz / 4 + 256) / 256, 256>>>(A_rows, nnz);
    scan1_kernel<<<nb_scan, SCAN_B>>>(n);
    scan23_kernel<<<(n + 255) / 256, 256>>>(n, nb_scan);

    int gemm_blocks    = (n + 511) / 512;
    int scatter_blocks = (nnz / 8 + 256) / 256;
    gemm_scatter_kernel<<<gemm_blocks + scatter_blocks, 256>>>(
        Hm, W1, A_rows, A_cols, A_vals, n, nnz, gemm_blocks);

    spmm1_kernel<<<(n + 63) / 64, 256>>>(b1, n);
    spmm2_epi_kernel<<<(n + 63) / 64, 256>>>(W2, b2, out, n);
}

// round 13
// speedup vs baseline: 1.6137x; 1.1178x over previous
#include <cuda_runtime.h>
#include <cuda_fp16.h>

typedef unsigned long long ull;

#define DQ    512
#define H1Q   16
#define CQ    40
#define N_MAX 100000
#define NNZ_MAX 3200000

#define TK     8                  // k-cols per tile
#define NT     (DQ / TK)          // 64 tiles
#define PADW   12                 // floats per staged row (8 + 4 pad)

#define CAP     128               // ELL slots per row (max expected deg ~59)
#define OVF_MAX 8192

// ------------------------------ scratch -------------------------------------
__device__ uint2 g_X1h[N_MAX * 4];           // H @ W1, fp16
__device__ uint2 g_Zh [N_MAX * 4];           // relu(A @ X1 + b1), fp16
__device__ int   g_cnt[N_MAX + 1];           // per-row degree; [N_MAX] = ovf count
__device__ int2  g_ell[(size_t)N_MAX * CAP]; // ELL: {col, val_bits}
__device__ int4  g_ovf[OVF_MAX];             // overflow: {row, col, val_bits, 0}

// ------------------------------ helpers -------------------------------------
__device__ __forceinline__ ull fma2(ull a, ull b, ull c) {
    ull d;
    asm("fma.rn.f32x2 %0, %1, %2, %3;" : "=l"(d) : "l"(a), "l"(b), "l"(c));
    return d;
}
__device__ __forceinline__ ull pack2(float x) {
    ull d;
    asm("mov.b64 %0, {%1, %1};" : "=l"(d) : "f"(x));
    return d;
}
__device__ __forceinline__ float2 unpack2(ull v) {
    float a, b;
    asm("mov.b64 {%0, %1}, %2;" : "=f"(a), "=f"(b) : "l"(v));
    return make_float2(a, b);
}
__device__ __forceinline__ unsigned h2pack(ull v) {
    float2 f = unpack2(v);
    __half2 h = __float22half2_rn(f);
    return *reinterpret_cast<unsigned*>(&h);
}
__device__ __forceinline__ float2 h2unpack(unsigned u) {
    __half2 h = *reinterpret_cast<__half2*>(&u);
    return __half22float2(h);
}
__device__ __forceinline__ unsigned smem_u32(const void* p) {
    return (unsigned)__cvta_generic_to_shared(p);
}
__device__ __forceinline__ void cp_async16(unsigned s, const void* g) {
    asm volatile("cp.async.cg.shared.global [%0], [%1], 16;" :: "r"(s), "l"(g));
}
__device__ __forceinline__ void cp_commit() {
    asm volatile("cp.async.commit_group;");
}
template <int N>
__device__ __forceinline__ void cp_wait() {
    asm volatile("cp.async.wait_group %0;" :: "n"(N));
}

__device__ __forceinline__ void ell_store(int r, int c, int vbits) {
    int s = atomicAdd(&g_cnt[r], 1);
    if (s < CAP) {
        g_ell[(size_t)r * CAP + s] = make_int2(c, vbits);
    } else {
        int o = atomicAdd(&g_cnt[N_MAX], 1);
        if (o < OVF_MAX) g_ovf[o] = make_int4(r, c, vbits, 0);
    }
}

// ------------------------------ fused GEMM + ELL scatter ---------------------
// gemm blocks (R9 config): 8 per-warp pipelines; warp owns 64 rows (2 rows/
// thread), TK=8, double-buffered cp.async, W1 broadcast from smem.
// scatter blocks: 8 edges/thread, builds ELL directly (no hist/scan needed).
__global__ void __launch_bounds__(256) gemm_scatter_kernel(
        const float* __restrict__ Hm, const float* __restrict__ W1,
        const int* __restrict__ rows, const int* __restrict__ cols,
        const float* __restrict__ vals, int n, int nnz, int gemm_blocks) {
    __shared__ ull   sW2[DQ * 8];               // 32KB  [k][pair0..7]
    __shared__ float sH[8][2][64 * PADW];       // 8 x 6KB

    if ((int)blockIdx.x < gemm_blocks) {
        int tid  = threadIdx.x;
        int warp = tid >> 5;
        int lane = tid & 31;
        int rbase = (blockIdx.x * 8 + warp) * 64;
        int ra = rbase + lane;
        int rb = ra + 32;

        // W via cp.async (group 0)
#pragma unroll
        for (int j = 0; j < 8; j++) {
            int i = tid + 256 * j;
            cp_async16(smem_u32(reinterpret_cast<float4*>(sW2) + i),
                       reinterpret_cast<const float4*>(W1) + i);
        }
        // stage tile 0 (group 0)
#pragma unroll
        for (int j = 0; j < 4; j++) {
            int i = lane + 32 * j;
            int r = i >> 1, q = i & 1;
            int grow = rbase + r;
            if (grow < n)
                cp_async16(smem_u32(&sH[warp][0][r * PADW + q * 4]),
                           Hm + (size_t)grow * DQ + q * 4);
        }
        cp_commit();

        ull accA[8], accB[8];
        ull z = pack2(0.f);
#pragma unroll
        for (int p = 0; p < 8; p++) { accA[p] = z; accB[p] = z; }

        const ulonglong2* wv = reinterpret_cast<const ulonglong2*>(sW2);

        for (int t = 0; t < NT; t++) {
            int buf = t & 1;
            if (t + 1 < NT) {
#pragma unroll
                for (int j = 0; j < 4; j++) {
                    int i = lane + 32 * j;
                    int r = i >> 1, q = i & 1;
                    int grow = rbase + r;
                    if (grow < n)
                        cp_async16(smem_u32(&sH[warp][buf ^ 1][r * PADW + q * 4]),
                                   Hm + (size_t)grow * DQ + (t + 1) * TK + q * 4);
                }
                cp_commit();
                cp_wait<1>();
            } else {
                cp_wait<0>();
            }
            __syncwarp();
            if (t == 0) __syncthreads();         // W visible to all warps

            const float* hrA = &sH[warp][buf][lane * PADW];
            const float* hrB = &sH[warp][buf][(lane + 32) * PADW];
#pragma unroll
            for (int q = 0; q < 2; q++) {
                float4 hA = *reinterpret_cast<const float4*>(hrA + q * 4);
                float4 hB = *reinterpret_cast<const float4*>(hrB + q * 4);
                float a4[4] = {hA.x, hA.y, hA.z, hA.w};
                float b4[4] = {hB.x, hB.y, hB.z, hB.w};
#pragma unroll
                for (int j = 0; j < 4; j++) {
                    int k = t * TK + q * 4 + j;
                    ull pa = pack2(a4[j]);
                    ull pb = pack2(b4[j]);
#pragma unroll
                    for (int p = 0; p < 4; p++) {
                        ulonglong2 w = wv[k * 4 + p];
                        accA[2 * p + 0] = fma2(pa, w.x, accA[2 * p + 0]);
                        accA[2 * p + 1] = fma2(pa, w.y, accA[2 * p + 1]);
                        accB[2 * p + 0] = fma2(pb, w.x, accB[2 * p + 0]);
                        accB[2 * p + 1] = fma2(pb, w.y, accB[2 * p + 1]);
                    }
                }
            }
            __syncwarp();
        }

        if (ra < n) {
            uint2* o = &g_X1h[(size_t)ra * 4];
#pragma unroll
            for (int q = 0; q < 4; q++)
                o[q] = make_uint2(h2pack(accA[2 * q]), h2pack(accA[2 * q + 1]));
        }
        if (rb < n) {
            uint2* o = &g_X1h[(size_t)rb * 4];
#pragma unroll
            for (int q = 0; q < 4; q++)
                o[q] = make_uint2(h2pack(accB[2 * q]), h2pack(accB[2 * q + 1]));
        }
    } else {
        int idx = (blockIdx.x - gemm_blocks) * 256 + threadIdx.x;
        int nv = nnz >> 3;                       // 8 edges per thread
        if (idx < nv) {
            const int4* r4p = reinterpret_cast<const int4*>(rows);
            const int4* c4p = reinterpret_cast<const int4*>(cols);
            const float4* v4p = reinterpret_cast<const float4*>(vals);
            int4   r0 = r4p[2 * idx],     r1 = r4p[2 * idx + 1];
            int4   c0 = c4p[2 * idx],     c1 = c4p[2 * idx + 1];
            float4 v0 = v4p[2 * idx],     v1 = v4p[2 * idx + 1];
            ell_store(r0.x, c0.x, __float_as_int(v0.x));
            ell_store(r0.y, c0.y, __float_as_int(v0.y));
            ell_store(r0.z, c0.z, __float_as_int(v0.z));
            ell_store(r0.w, c0.w, __float_as_int(v0.w));
            ell_store(r1.x, c1.x, __float_as_int(v1.x));
            ell_store(r1.y, c1.y, __float_as_int(v1.y));
            ell_store(r1.z, c1.z, __float_as_int(v1.z));
            ell_store(r1.w, c1.w, __float_as_int(v1.w));
        } else if (idx == nv) {
            for (int e = nv * 8; e < nnz; e++)
                ell_store(rows[e], cols[e], __float_as_int(vals[e]));
        }
    }
}

// ------------------------------ SpMM gather core (MLP=8) ---------------------
__device__ __forceinline__ float4 gather_row(const uint2* __restrict__ X,
                                             const int2* __restrict__ ed,
                                             int deg, int sub) {
    float4 acc = make_float4(0, 0, 0, 0);
    int i = 0;
    for (; i + 8 <= deg; i += 8) {
        int2  e[8];
        uint2 x[8];
#pragma unroll
        for (int j = 0; j < 8; j++) e[j] = ed[i + j];
#pragma unroll
        for (int j = 0; j < 8; j++) x[j] = X[(size_t)e[j].x * 4 + sub];
#pragma unroll
        for (int j = 0; j < 8; j++) {
            float v = __int_as_float(e[j].y);
            float2 lo = h2unpack(x[j].x), hi = h2unpack(x[j].y);
            acc.x = fmaf(v, lo.x, acc.x); acc.y = fmaf(v, lo.y, acc.y);
            acc.z = fmaf(v, hi.x, acc.z); acc.w = fmaf(v, hi.y, acc.w);
        }
    }
    for (; i < deg; i++) {
        int2 e = ed[i];
        float v = __int_as_float(e.y);
        uint2 xh = X[(size_t)e.x * 4 + sub];
        float2 lo = h2unpack(xh.x), hi = h2unpack(xh.y);
        acc.x = fmaf(v, lo.x, acc.x); acc.y = fmaf(v, lo.y, acc.y);
        acc.z = fmaf(v, hi.x, acc.z); acc.w = fmaf(v, hi.y, acc.w);
    }
    return acc;
}

// overflow edges (normally zero) — correctness safety net
__device__ __forceinline__ float4 gather_ovf(const uint2* __restrict__ X,
                                             int row, int sub, float4 acc) {
    int novf = g_cnt[N_MAX];
    for (int i = 0; i < novf && i < OVF_MAX; i++) {
        int4 e = g_ovf[i];
        if (e.x == row) {
            float v = __int_as_float(e.z);
            uint2 xh = X[(size_t)e.y * 4 + sub];
            float2 lo = h2unpack(xh.x), hi = h2unpack(xh.y);
            acc.x = fmaf(v, lo.x, acc.x); acc.y = fmaf(v, lo.y, acc.y);
            acc.z = fmaf(v, hi.x, acc.z); acc.w = fmaf(v, hi.y, acc.w);
        }
    }
    return acc;
}

// ------------------------------ SpMM 1 ---------------------------------------
__global__ void spmm1_kernel(const float* __restrict__ b1, int n) {
    int wg   = (blockIdx.x * blockDim.x + threadIdx.x) >> 5;
    int lane = threadIdx.x & 31;
    int rloc = lane >> 2, sub = lane & 3;
    int row  = wg * 8 + rloc;
    if (row >= n) return;

    int deg = min(g_cnt[row], CAP);
    const float4 b = reinterpret_cast<const float4*>(b1)[sub];

    float4 acc = gather_row(g_X1h, g_ell + (size_t)row * CAP, deg, sub);
    acc = gather_ovf(g_X1h, row, sub, acc);

    float2 z0 = make_float2(fmaxf(acc.x + b.x, 0.f), fmaxf(acc.y + b.y, 0.f));
    float2 z1 = make_float2(fmaxf(acc.z + b.z, 0.f), fmaxf(acc.w + b.w, 0.f));
    __half2 h0 = __float22half2_rn(z0);
    __half2 h1 = __float22half2_rn(z1);
    g_Zh[(size_t)row * 4 + sub] =
        make_uint2(*reinterpret_cast<unsigned*>(&h0), *reinterpret_cast<unsigned*>(&h1));
}

// ------------------------------ SpMM 2 + epilogue ----------------------------
__global__ void __launch_bounds__(256) spmm2_epi_kernel(
        const float* __restrict__ W2, const float* __restrict__ b2,
        float* __restrict__ out, int n) {
    __shared__ float sY[64 * 17];
    __shared__ float sW[H1Q * CQ];
    __shared__ float sB[CQ];

    for (int i = threadIdx.x; i < H1Q * CQ; i += blockDim.x) sW[i] = W2[i];
    if (threadIdx.x < CQ) sB[threadIdx.x] = b2[threadIdx.x];

    int warp  = threadIdx.x >> 5;
    int lane  = threadIdx.x & 31;
    int rloc  = warp * 8 + (lane >> 2);
    int sub   = lane & 3;
    int rbase = blockIdx.x * 64;
    int row   = rbase + rloc;

    float4 acc = make_float4(0, 0, 0, 0);
    if (row < n) {
        int deg = min(g_cnt[row], CAP);
        acc = gather_row(g_Zh, g_ell + (size_t)row * CAP, deg, sub);
        acc = gather_ovf(g_Zh, row, sub, acc);
    }
    float* sy = &sY[rloc * 17 + sub * 4];
    sy[0] = acc.x; sy[1] = acc.y; sy[2] = acc.z; sy[3] = acc.w;
    __syncthreads();

    // epilogue: thread t -> row t>>2, columns [10*(t&3), 10*(t&3)+10)
    int t    = threadIdx.x;
    int erow = t >> 2;
    int part = t & 3;
    if (rbase + erow < n) {
        float y[16];
#pragma unroll
        for (int k = 0; k < 16; k++) y[k] = sY[erow * 17 + k];

        float o[10];
#pragma unroll
        for (int c = 0; c < 10; c++) o[c] = sB[part * 10 + c];
#pragma unroll
        for (int k = 0; k < H1Q; k++) {
            float h = y[k];
#pragma unroll
            for (int c = 0; c < 10; c++)
                o[c] = fmaf(h, sW[k * CQ + part * 10 + c], o[c]);
        }
        float m = 0.f;                      // relu floor
#pragma unroll
        for (int c = 0; c < 10; c++) {
            o[c] = fmaxf(o[c], 0.f);
            m = fmaxf(m, o[c]);
        }
        m = fmaxf(m, __shfl_xor_sync(0xffffffffu, m, 1));
        m = fmaxf(m, __shfl_xor_sync(0xffffffffu, m, 2));
        float s = 0.f;
#pragma unroll
        for (int c = 0; c < 10; c++) s += __expf(o[c] - m);
        s += __shfl_xor_sync(0xffffffffu, s, 1);
        s += __shfl_xor_sync(0xffffffffu, s, 2);
        float l = __logf(s) + m;

        float2* op = reinterpret_cast<float2*>(
            out + (size_t)(rbase + erow) * CQ + part * 10);
#pragma unroll
        for (int q = 0; q < 5; q++)
            op[q] = make_float2(o[2 * q] - l, o[2 * q + 1] - l);
    }
}

// ---------------------------------------------------------------------------
// Inputs (metadata order): H, A_vals, W1, b1, W2, b2, A_rows, A_cols
// ---------------------------------------------------------------------------
extern "C" void kernel_launch(void* const* d_in, const int* in_sizes, int n_in,
                              void* d_out, int out_size) {
    const float* Hm     = (const float*)d_in[0];
    const float* A_vals = (const float*)d_in[1];
    const float* W1     = (const float*)d_in[2];
    const float* b1     = (const float*)d_in[3];
    const float* W2     = (const float*)d_in[4];
    const float* b2     = (const float*)d_in[5];
    const int*   A_rows = (const int*)d_in[6];
    const int*   A_cols = (const int*)d_in[7];

    int n   = in_sizes[0] / DQ;
    int nnz = in_sizes[1];
    float* out = (float*)d_out;

    void* cnt_ptr = nullptr;
    cudaGetSymbolAddress(&cnt_ptr, g_cnt);
    cudaMemsetAsync(cnt_ptr, 0, (size_t)(N_MAX + 1) * sizeof(int), 0);

    int gemm_blocks    = (n + 511) / 512;
    int scatter_blocks = (nnz / 8 + 256) / 256;
    gemm_scatter_kernel<<<gemm_blocks + scatter_blocks, 256>>>(
        Hm, W1, A_rows, A_cols, A_vals, n, nnz, gemm_blocks);

    spmm1_kernel<<<(n + 63) / 64, 256>>>(b1, n);
    spmm2_epi_kernel<<<(n + 63) / 64, 256>>>(W2, b2, out, n);
}